// round 1
// baseline (speedup 1.0000x reference)
#include <cuda_runtime.h>
#include <cuda_bf16.h>

// PointWarping2: Nadaraya-Watson Gaussian kernel regression.
// out[b,c,n] = xyz2[b,c,n] - (sum_m w*f1[m,c]) / (sum_m w),
//   w = exp(-|x2 - (x1+f1)|^2 / scale^2)
//
// Strategy:
//   prep:  pack sources as A=(2L*y.x, 2L*y.y, 2L*y.z, -L*|y|^2), F=(f.x,f.y,f.z,0)
//          with L = log2(e)/scale^2, so per-pair weight = ex2(fma-chain).
//   main:  split-K over sources (MSPLIT), smem broadcast tiles, 1 thread/query.
//   fin:   reduce MSPLIT partials, divide, write output.

#define Bx 2
#define Cx 3
#define N1x 8192
#define N2x 8192
#define NQ (Bx * N2x)          // 16384 total queries
#define MSPLIT 4
#define MCHUNK (N1x / MSPLIT)   // 2048 sources per split
#define TILE 1024
#define BLK 128                 // threads per main block

__device__ float4 g_srcA[Bx * N1x];
__device__ float4 g_srcF[Bx * N1x];
__device__ float4 g_partial[MSPLIT * NQ];

__device__ __forceinline__ float ex2f(float x) {
    float y;
    asm("ex2.approx.ftz.f32 %0, %1;" : "=f"(y) : "f"(x));
    return y;
}

// resol_factor may arrive as int32 or float32; disambiguate by bit pattern.
__device__ __forceinline__ float read_scale(const void* p) {
    int iv = *(const int*)p;
    float f;
    if (iv > 0 && iv < 100000) f = (float)iv;          // small positive int
    else f = __int_as_float(iv);                        // float bit pattern
    return 1.0f * f;                                    // INITIAL_RADIUS = 1.0
}

__global__ void prep_kernel(const float* __restrict__ xyz1,
                            const float* __restrict__ flow1,
                            const void* __restrict__ resol) {
    int idx = blockIdx.x * blockDim.x + threadIdx.x;
    if (idx >= Bx * N1x) return;
    int b = idx >> 13;            // / 8192
    int m = idx & (N1x - 1);
    const float* x1b = xyz1 + b * Cx * N1x;
    const float* f1b = flow1 + b * Cx * N1x;
    float fx = f1b[0 * N1x + m];
    float fy = f1b[1 * N1x + m];
    float fz = f1b[2 * N1x + m];
    float yx = x1b[0 * N1x + m] + fx;
    float yy = x1b[1 * N1x + m] + fy;
    float yz = x1b[2 * N1x + m] + fz;
    float scale = read_scale(resol);
    float L = 1.4426950408889634f / (scale * scale);
    float cm = -L * (yx * yx + yy * yy + yz * yz);
    g_srcA[idx] = make_float4(2.0f * L * yx, 2.0f * L * yy, 2.0f * L * yz, cm);
    g_srcF[idx] = make_float4(fx, fy, fz, 0.0f);
}

__global__ __launch_bounds__(BLK) void main_kernel(
    const float* __restrict__ xyz2, const void* __restrict__ resol) {
    __shared__ float4 sA[TILE];
    __shared__ float4 sF[TILE];

    int q = blockIdx.x * BLK + threadIdx.x;      // all threads in block share b
    int b = q >> 13;
    int n = q & (N2x - 1);
    const float* x2b = xyz2 + b * Cx * N2x;
    float qx = x2b[0 * N2x + n];
    float qy = x2b[1 * N2x + n];
    float qz = x2b[2 * N2x + n];
    float scale = read_scale(resol);
    float L = 1.4426950408889634f / (scale * scale);
    float cn = -L * (qx * qx + qy * qy + qz * qz);

    int m0 = blockIdx.y * MCHUNK;
    const float4* srcA = g_srcA + b * N1x;
    const float4* srcF = g_srcF + b * N1x;

    float nx = 0.f, ny = 0.f, nz = 0.f, den = 0.f;

    for (int mt = m0; mt < m0 + MCHUNK; mt += TILE) {
        // cooperative tile load
        #pragma unroll
        for (int i = threadIdx.x; i < TILE; i += BLK) {
            sA[i] = srcA[mt + i];
            sF[i] = srcF[mt + i];
        }
        __syncthreads();

        #pragma unroll 8
        for (int j = 0; j < TILE; j++) {
            float4 a = sA[j];
            float4 f = sF[j];
            float arg = cn + a.w;
            arg = fmaf(qx, a.x, arg);
            arg = fmaf(qy, a.y, arg);
            arg = fmaf(qz, a.z, arg);
            float w = ex2f(arg);
            nx = fmaf(w, f.x, nx);
            ny = fmaf(w, f.y, ny);
            nz = fmaf(w, f.z, nz);
            den += w;
        }
        __syncthreads();
    }

    g_partial[blockIdx.y * NQ + q] = make_float4(nx, ny, nz, den);
}

__global__ void finalize_kernel(const float* __restrict__ xyz2,
                                float* __restrict__ out) {
    int q = blockIdx.x * blockDim.x + threadIdx.x;
    if (q >= NQ) return;
    int b = q >> 13;
    int n = q & (N2x - 1);
    float nx = 0.f, ny = 0.f, nz = 0.f, den = 0.f;
    #pragma unroll
    for (int s = 0; s < MSPLIT; s++) {
        float4 p = g_partial[s * NQ + q];
        nx += p.x; ny += p.y; nz += p.z; den += p.w;
    }
    float inv = 1.0f / den;
    const float* x2b = xyz2 + b * Cx * N2x;
    float* ob = out + b * Cx * N2x;
    ob[0 * N2x + n] = x2b[0 * N2x + n] - nx * inv;
    ob[1 * N2x + n] = x2b[1 * N2x + n] - ny * inv;
    ob[2 * N2x + n] = x2b[2 * N2x + n] - nz * inv;
}

extern "C" void kernel_launch(void* const* d_in, const int* in_sizes, int n_in,
                              void* d_out, int out_size) {
    const float* xyz1  = (const float*)d_in[0];
    const float* xyz2  = (const float*)d_in[1];
    const float* flow1 = (const float*)d_in[2];
    const void*  resol = d_in[3];
    float* out = (float*)d_out;

    prep_kernel<<<(Bx * N1x + 255) / 256, 256>>>(xyz1, flow1, resol);

    dim3 grid(NQ / BLK, MSPLIT);
    main_kernel<<<grid, BLK>>>(xyz2, resol);

    finalize_kernel<<<(NQ + 255) / 256, 256>>>(xyz2, out);
}

// round 2
// speedup vs baseline: 1.3544x; 1.3544x over previous
#include <cuda_runtime.h>
#include <cuda_bf16.h>

// PointWarping2 — Nadaraya-Watson Gaussian regression, f32x2-packed version.
//
// Math: out = x2 - num/den, num = sum_m w*f1[m], den = sum_m w,
//   w = exp(-|x2-(x1+f1)|^2/s^2).
// The per-query factor exp(-L|q|^2) cancels in num/den, so we use
//   w' = ex2( q . a_xyz + a_w ),  a = (2L*y, -L*|y|^2), L = log2(e)/s^2.
//
// Two sources are processed per fma.rn.f32x2 instruction (sm_103a packed fp32).

#define Bx 2
#define Cx 3
#define N1x 8192
#define N2x 8192
#define NQ (Bx * N2x)            // 16384 queries
#define MSPLIT 8
#define TILE 1024                 // sources per block (== N1x/MSPLIT)
#define PAIRS (TILE / 2)          // 512 packed pairs per tile
#define BLK 128
#define PPB (N1x / 2)             // 4096 pairs per batch

typedef unsigned long long ull;

// Pair-packed source data (produced by prep):
//  g_p0[p] = (ax0, ax1, ay0, ay1)
//  g_p1[p] = (az0, az1, aw0, aw1)
//  g_p2[p] = (fx0, fx1, fy0, fy1)
//  g_p3[p] = (fz0, fz1)
__device__ float4 g_p0[Bx * PPB];
__device__ float4 g_p1[Bx * PPB];
__device__ float4 g_p2[Bx * PPB];
__device__ float2 g_p3[Bx * PPB];
__device__ float4 g_partial[MSPLIT * NQ];

__device__ __forceinline__ float ex2f(float x) {
    float y;
    asm("ex2.approx.ftz.f32 %0, %1;" : "=f"(y) : "f"(x));
    return y;
}
__device__ __forceinline__ ull fma2(ull a, ull b, ull c) {
    ull d;
    asm("fma.rn.f32x2 %0, %1, %2, %3;" : "=l"(d) : "l"(a), "l"(b), "l"(c));
    return d;
}
__device__ __forceinline__ ull add2(ull a, ull b) {
    ull d;
    asm("add.rn.f32x2 %0, %1, %2;" : "=l"(d) : "l"(a), "l"(b));
    return d;
}
__device__ __forceinline__ ull pack2(float lo, float hi) {
    ull d;
    asm("mov.b64 %0, {%1, %2};" : "=l"(d) : "f"(lo), "f"(hi));
    return d;
}
__device__ __forceinline__ void unpack2(ull v, float& lo, float& hi) {
    asm("mov.b64 {%0, %1}, %2;" : "=f"(lo), "=f"(hi) : "l"(v));
}

// resol_factor may arrive as int32 or float32 bits; disambiguate.
__device__ __forceinline__ float read_scale(const void* p) {
    int iv = *(const int*)p;
    float f;
    if (iv > 0 && iv < 100000) f = (float)iv;
    else f = __int_as_float(iv);
    return 1.0f * f;  // INITIAL_RADIUS = 1.0
}

__global__ void prep_kernel(const float* __restrict__ xyz1,
                            const float* __restrict__ flow1,
                            const void* __restrict__ resol) {
    int p = blockIdx.x * blockDim.x + threadIdx.x;
    if (p >= Bx * PPB) return;
    int b = p >> 12;               // / PPB (4096)
    int m = (p & (PPB - 1)) * 2;
    const float* x1b = xyz1 + b * Cx * N1x;
    const float* f1b = flow1 + b * Cx * N1x;
    float scale = read_scale(resol);
    float L = 1.4426950408889634f / (scale * scale);

    float fx0 = f1b[0 * N1x + m],     fy0 = f1b[1 * N1x + m],     fz0 = f1b[2 * N1x + m];
    float fx1 = f1b[0 * N1x + m + 1], fy1 = f1b[1 * N1x + m + 1], fz1 = f1b[2 * N1x + m + 1];
    float yx0 = x1b[0 * N1x + m] + fx0,     yy0 = x1b[1 * N1x + m] + fy0,     yz0 = x1b[2 * N1x + m] + fz0;
    float yx1 = x1b[0 * N1x + m + 1] + fx1, yy1 = x1b[1 * N1x + m + 1] + fy1, yz1 = x1b[2 * N1x + m + 1] + fz1;
    float aw0 = -L * (yx0 * yx0 + yy0 * yy0 + yz0 * yz0);
    float aw1 = -L * (yx1 * yx1 + yy1 * yy1 + yz1 * yz1);
    float t = 2.0f * L;

    g_p0[p] = make_float4(t * yx0, t * yx1, t * yy0, t * yy1);
    g_p1[p] = make_float4(t * yz0, t * yz1, aw0, aw1);
    g_p2[p] = make_float4(fx0, fx1, fy0, fy1);
    g_p3[p] = make_float2(fz0, fz1);
}

__global__ __launch_bounds__(BLK) void main_kernel(const float* __restrict__ xyz2) {
    __shared__ float4 s0[PAIRS];
    __shared__ float4 s1[PAIRS];
    __shared__ float4 s2[PAIRS];
    __shared__ float2 s3[PAIRS];

    int q = blockIdx.x * BLK + threadIdx.x;   // block is within one batch
    int b = q >> 13;
    int n = q & (N2x - 1);

    int pbase = b * PPB + blockIdx.y * PAIRS;

    // cooperative tile load
    #pragma unroll
    for (int i = threadIdx.x; i < PAIRS; i += BLK) {
        s0[i] = g_p0[pbase + i];
        s1[i] = g_p1[pbase + i];
        s2[i] = g_p2[pbase + i];
        s3[i] = g_p3[pbase + i];
    }

    const float* x2b = xyz2 + b * Cx * N2x;
    float qx = x2b[0 * N2x + n];
    float qy = x2b[1 * N2x + n];
    float qz = x2b[2 * N2x + n];
    ull qx2 = pack2(qx, qx);
    ull qy2 = pack2(qy, qy);
    ull qz2 = pack2(qz, qz);

    __syncthreads();

    const ulonglong2* u0 = (const ulonglong2*)s0;
    const ulonglong2* u1 = (const ulonglong2*)s1;
    const ulonglong2* u2 = (const ulonglong2*)s2;
    const ull*        u3 = (const ull*)s3;

    ull nx2 = 0, ny2 = 0, nz2 = 0, dn2 = 0;

    #pragma unroll 8
    for (int j = 0; j < PAIRS; j++) {
        ulonglong2 a01 = u0[j];   // ax2, ay2
        ulonglong2 a23 = u1[j];   // az2, aw2
        ulonglong2 f01 = u2[j];   // fx2, fy2
        ull        fz2 = u3[j];
        ull arg = fma2(qx2, a01.x, fma2(qy2, a01.y, fma2(qz2, a23.x, a23.y)));
        float al, ah;
        unpack2(arg, al, ah);
        ull w2 = pack2(ex2f(al), ex2f(ah));
        nx2 = fma2(w2, f01.x, nx2);
        ny2 = fma2(w2, f01.y, ny2);
        nz2 = fma2(w2, fz2, nz2);
        dn2 = add2(dn2, w2);
    }

    float a, c;
    float4 r;
    unpack2(nx2, a, c); r.x = a + c;
    unpack2(ny2, a, c); r.y = a + c;
    unpack2(nz2, a, c); r.z = a + c;
    unpack2(dn2, a, c); r.w = a + c;
    g_partial[blockIdx.y * NQ + q] = r;
}

__global__ void finalize_kernel(const float* __restrict__ xyz2,
                                float* __restrict__ out) {
    int q = blockIdx.x * blockDim.x + threadIdx.x;
    if (q >= NQ) return;
    int b = q >> 13;
    int n = q & (N2x - 1);
    float nx = 0.f, ny = 0.f, nz = 0.f, den = 0.f;
    #pragma unroll
    for (int s = 0; s < MSPLIT; s++) {
        float4 p = g_partial[s * NQ + q];
        nx += p.x; ny += p.y; nz += p.z; den += p.w;
    }
    float inv = 1.0f / den;
    const float* x2b = xyz2 + b * Cx * N2x;
    float* ob = out + b * Cx * N2x;
    ob[0 * N2x + n] = x2b[0 * N2x + n] - nx * inv;
    ob[1 * N2x + n] = x2b[1 * N2x + n] - ny * inv;
    ob[2 * N2x + n] = x2b[2 * N2x + n] - nz * inv;
}

extern "C" void kernel_launch(void* const* d_in, const int* in_sizes, int n_in,
                              void* d_out, int out_size) {
    const float* xyz1  = (const float*)d_in[0];
    const float* xyz2  = (const float*)d_in[1];
    const float* flow1 = (const float*)d_in[2];
    const void*  resol = d_in[3];
    float* out = (float*)d_out;

    prep_kernel<<<(Bx * PPB + 255) / 256, 256>>>(xyz1, flow1, resol);

    dim3 grid(NQ / BLK, MSPLIT);
    main_kernel<<<grid, BLK>>>(xyz2);

    finalize_kernel<<<(NQ + 255) / 256, 256>>>(xyz2, out);
}

// round 3
// speedup vs baseline: 1.6965x; 1.2526x over previous
#include <cuda_runtime.h>
#include <cuda_bf16.h>

// PointWarping2 — Nadaraya-Watson Gaussian regression.
// f32x2-packed FMA, 2 sources x 2 queries per inner iteration (amortize LDS),
// prep fused into tile load, split-K over sources.
//
// w' = ex2( q . a_xyz + a_w ), a = (2L*y, -L*|y|^2), L = log2(e)/s^2
// (per-query factor 2^{L|q|^2} cancels in num/den).

#define Bx 2
#define N1x 8192
#define N2x 8192
#define NQ (Bx * N2x)           // 16384 queries
#define MSPLIT 16
#define TILE 512                 // sources per split
#define PAIRS (TILE / 2)         // 256 packed source-pairs per tile
#define BLK 128
#define QPT 2                    // queries per thread
#define QPB (BLK * QPT)          // 256 queries per block

typedef unsigned long long ull;

__device__ float4 g_partial[MSPLIT * NQ];

__device__ __forceinline__ float ex2f(float x) {
    float y;
    asm("ex2.approx.ftz.f32 %0, %1;" : "=f"(y) : "f"(x));
    return y;
}
__device__ __forceinline__ ull fma2(ull a, ull b, ull c) {
    ull d;
    asm("fma.rn.f32x2 %0, %1, %2, %3;" : "=l"(d) : "l"(a), "l"(b), "l"(c));
    return d;
}
__device__ __forceinline__ ull add2(ull a, ull b) {
    ull d;
    asm("add.rn.f32x2 %0, %1, %2;" : "=l"(d) : "l"(a), "l"(b));
    return d;
}
__device__ __forceinline__ ull pack2(float lo, float hi) {
    ull d;
    asm("mov.b64 %0, {%1, %2};" : "=l"(d) : "f"(lo), "f"(hi));
    return d;
}
__device__ __forceinline__ void unpack2(ull v, float& lo, float& hi) {
    asm("mov.b64 {%0, %1}, %2;" : "=f"(lo), "=f"(hi) : "l"(v));
}

// resol_factor may arrive as int32 or float32 bits; disambiguate.
__device__ __forceinline__ float read_scale(const void* p) {
    int iv = *(const int*)p;
    float f;
    if (iv > 0 && iv < 100000) f = (float)iv;
    else f = __int_as_float(iv);
    return 1.0f * f;  // INITIAL_RADIUS = 1.0
}

__global__ __launch_bounds__(BLK) void main_kernel(
    const float* __restrict__ xyz1, const float* __restrict__ xyz2,
    const float* __restrict__ flow1, const void* __restrict__ resol) {
    __shared__ float4 s0[PAIRS];   // (ax0,ax1, ay0,ay1)
    __shared__ float4 s1[PAIRS];   // (az0,az1, aw0,aw1)
    __shared__ float4 s2[PAIRS];   // (fx0,fx1, fy0,fy1)
    __shared__ float2 s3[PAIRS];   // (fz0,fz1)

    int qbase = blockIdx.x * QPB;          // block stays within one batch
    int b = qbase >> 13;
    int q0 = qbase + threadIdx.x;
    int q1 = q0 + BLK;
    int n0 = q0 & (N2x - 1);
    int n1 = q1 & (N2x - 1);

    float scale = read_scale(resol);
    float L = 1.4426950408889634f / (scale * scale);
    float t2 = 2.0f * L;

    // ---- fused prep: build packed source tile from raw inputs ----
    const float* x1b = xyz1 + b * 3 * N1x;
    const float* f1b = flow1 + b * 3 * N1x;
    int m0 = blockIdx.y * TILE;
    #pragma unroll
    for (int i = threadIdx.x; i < PAIRS; i += BLK) {
        int m = m0 + 2 * i;
        float2 xx = *(const float2*)(x1b + m);
        float2 xy = *(const float2*)(x1b + N1x + m);
        float2 xz = *(const float2*)(x1b + 2 * N1x + m);
        float2 fx = *(const float2*)(f1b + m);
        float2 fy = *(const float2*)(f1b + N1x + m);
        float2 fz = *(const float2*)(f1b + 2 * N1x + m);
        float yx0 = xx.x + fx.x, yx1 = xx.y + fx.y;
        float yy0 = xy.x + fy.x, yy1 = xy.y + fy.y;
        float yz0 = xz.x + fz.x, yz1 = xz.y + fz.y;
        s0[i] = make_float4(t2 * yx0, t2 * yx1, t2 * yy0, t2 * yy1);
        s1[i] = make_float4(t2 * yz0, t2 * yz1,
                            -L * (yx0 * yx0 + yy0 * yy0 + yz0 * yz0),
                            -L * (yx1 * yx1 + yy1 * yy1 + yz1 * yz1));
        s2[i] = make_float4(fx.x, fx.y, fy.x, fy.y);
        s3[i] = make_float2(fz.x, fz.y);
    }

    // ---- query registers (2 queries per thread) ----
    const float* x2b = xyz2 + b * 3 * N2x;
    float qx0 = x2b[n0], qy0 = x2b[N2x + n0], qz0 = x2b[2 * N2x + n0];
    float qx1 = x2b[n1], qy1 = x2b[N2x + n1], qz1 = x2b[2 * N2x + n1];
    ull qx20 = pack2(qx0, qx0), qy20 = pack2(qy0, qy0), qz20 = pack2(qz0, qz0);
    ull qx21 = pack2(qx1, qx1), qy21 = pack2(qy1, qy1), qz21 = pack2(qz1, qz1);

    __syncthreads();

    const ulonglong2* u0 = (const ulonglong2*)s0;
    const ulonglong2* u1 = (const ulonglong2*)s1;
    const ulonglong2* u2 = (const ulonglong2*)s2;
    const ull*        u3 = (const ull*)s3;

    ull nx0 = 0, ny0 = 0, nz0 = 0, d0 = 0;
    ull nx1 = 0, ny1 = 0, nz1 = 0, d1 = 0;

    #pragma unroll 4
    for (int j = 0; j < PAIRS; j++) {
        ulonglong2 a01 = u0[j];   // ax2, ay2
        ulonglong2 a23 = u1[j];   // az2, aw2
        ulonglong2 f01 = u2[j];   // fx2, fy2
        ull        fz2 = u3[j];
        ull arg0 = fma2(qx20, a01.x, fma2(qy20, a01.y, fma2(qz20, a23.x, a23.y)));
        ull arg1 = fma2(qx21, a01.x, fma2(qy21, a01.y, fma2(qz21, a23.x, a23.y)));
        float al, ah;
        unpack2(arg0, al, ah);
        ull w0 = pack2(ex2f(al), ex2f(ah));
        unpack2(arg1, al, ah);
        ull w1 = pack2(ex2f(al), ex2f(ah));
        nx0 = fma2(w0, f01.x, nx0);
        ny0 = fma2(w0, f01.y, ny0);
        nz0 = fma2(w0, fz2, nz0);
        d0  = add2(d0, w0);
        nx1 = fma2(w1, f01.x, nx1);
        ny1 = fma2(w1, f01.y, ny1);
        nz1 = fma2(w1, fz2, nz1);
        d1  = add2(d1, w1);
    }

    float a, c;
    float4 r0, r1;
    unpack2(nx0, a, c); r0.x = a + c;
    unpack2(ny0, a, c); r0.y = a + c;
    unpack2(nz0, a, c); r0.z = a + c;
    unpack2(d0,  a, c); r0.w = a + c;
    unpack2(nx1, a, c); r1.x = a + c;
    unpack2(ny1, a, c); r1.y = a + c;
    unpack2(nz1, a, c); r1.z = a + c;
    unpack2(d1,  a, c); r1.w = a + c;
    g_partial[blockIdx.y * NQ + q0] = r0;
    g_partial[blockIdx.y * NQ + q1] = r1;
}

__global__ void finalize_kernel(const float* __restrict__ xyz2,
                                float* __restrict__ out) {
    int q = blockIdx.x * blockDim.x + threadIdx.x;
    if (q >= NQ) return;
    int b = q >> 13;
    int n = q & (N2x - 1);
    float nx = 0.f, ny = 0.f, nz = 0.f, den = 0.f;
    #pragma unroll
    for (int s = 0; s < MSPLIT; s++) {
        float4 p = g_partial[s * NQ + q];
        nx += p.x; ny += p.y; nz += p.z; den += p.w;
    }
    float inv = 1.0f / den;
    const float* x2b = xyz2 + b * 3 * N2x;
    float* ob = out + b * 3 * N2x;
    ob[0 * N2x + n] = x2b[0 * N2x + n] - nx * inv;
    ob[1 * N2x + n] = x2b[1 * N2x + n] - ny * inv;
    ob[2 * N2x + n] = x2b[2 * N2x + n] - nz * inv;
}

extern "C" void kernel_launch(void* const* d_in, const int* in_sizes, int n_in,
                              void* d_out, int out_size) {
    const float* xyz1  = (const float*)d_in[0];
    const float* xyz2  = (const float*)d_in[1];
    const float* flow1 = (const float*)d_in[2];
    const void*  resol = d_in[3];
    float* out = (float*)d_out;

    dim3 grid(NQ / QPB, MSPLIT);
    main_kernel<<<grid, BLK>>>(xyz1, xyz2, flow1, resol);

    finalize_kernel<<<(NQ + 255) / 256, 256>>>(xyz2, out);
}